// round 15
// baseline (speedup 1.0000x reference)
#include <cuda_runtime.h>
#include <cuda_bf16.h>
#include <math.h>
#include <stdint.h>

// Problem constants
#define B16    16
#define L64    64
#define DM512  512
#define NCTX   3131
#define DINPROJ 1042
#define CONVDIM 514
#define MROWS  50096            // 16*3131

// Scratch (static device arrays; zero-initialized, allocation-free)
__device__ float S_zx [B16*L64*DINPROJ];
__device__ float S_x  [B16*L64*DM512];
__device__ float S_ys [2*B16*L64*DM512];
// split-bf16 operands (pre-pipeline)
__device__ __nv_bfloat16 S_uhi [B16*L64*DM512];
__device__ __nv_bfloat16 S_ulo [B16*L64*DM512];
__device__ __nv_bfloat16 S_ynhi[B16*L64*DM512];
__device__ __nv_bfloat16 S_ynlo[B16*L64*DM512];
__device__ __nv_bfloat16 S_outhi[B16*L64*DM512];
__device__ __nv_bfloat16 S_outlo[B16*L64*DM512];
__device__ __nv_bfloat16 S_W1hi[1152*DM512];
__device__ __nv_bfloat16 S_W1lo[1152*DM512];
__device__ __nv_bfloat16 S_W2hi[DM512*DM512];
__device__ __nv_bfloat16 S_W2lo[DM512*DM512];
__device__ __nv_bfloat16 S_Whi [DM512*DM512];
__device__ __nv_bfloat16 S_Wlo [DM512*DM512];
// Pt fp32 (tf32-pre-rounded): Pt[b][d][hg], natural layout
__device__ float S_Pt[(size_t)B16*DM512*DM512];

// ---- helpers ---------------------------------------------------------------
#define GDC_WAIT() asm volatile("griddepcontrol.wait;" ::: "memory")

__device__ __forceinline__ void mma16816(float* c, const uint32_t* a, const uint32_t* b) {
    asm volatile(
        "mma.sync.aligned.m16n8k16.row.col.f32.bf16.bf16.f32 "
        "{%0,%1,%2,%3}, {%4,%5,%6,%7}, {%8,%9}, {%0,%1,%2,%3};"
        : "+f"(c[0]), "+f"(c[1]), "+f"(c[2]), "+f"(c[3])
        : "r"(a[0]), "r"(a[1]), "r"(a[2]), "r"(a[3]), "r"(b[0]), "r"(b[1]));
}
__device__ __forceinline__ void mma_tf32(float* c, const uint32_t* a, const uint32_t* b) {
    asm volatile(
        "mma.sync.aligned.m16n8k8.row.col.f32.tf32.tf32.f32 "
        "{%0,%1,%2,%3}, {%4,%5,%6,%7}, {%8,%9}, {%0,%1,%2,%3};"
        : "+f"(c[0]), "+f"(c[1]), "+f"(c[2]), "+f"(c[3])
        : "r"(a[0]), "r"(a[1]), "r"(a[2]), "r"(a[3]), "r"(b[0]), "r"(b[1]));
}
__device__ __forceinline__ float to_tf32(float x) {
    uint32_t r;
    asm("cvt.rna.tf32.f32 %0, %1;" : "=r"(r) : "f"(x));
    return __uint_as_float(r);
}
__device__ __forceinline__ void bsplit(float v, __nv_bfloat16& h, __nv_bfloat16& l) {
    h = __float2bfloat16(v);
    l = __float2bfloat16(v - __bfloat162float(h));
}
__device__ __forceinline__ void cp16(void* dst, const void* src) {
    uint32_t d = (uint32_t)__cvta_generic_to_shared(dst);
    asm volatile("cp.async.cg.shared.global [%0], [%1], 16;" :: "r"(d), "l"(src));
}
// predicated 16B cp.async: src_size=0 zero-fills dst (OOB rows)
__device__ __forceinline__ void cp16p(void* dst, const void* src, bool pred) {
    uint32_t d = (uint32_t)__cvta_generic_to_shared(dst);
    int sz = pred ? 16 : 0;
    asm volatile("cp.async.cg.shared.global [%0], [%1], 16, %2;" :: "r"(d), "l"(src), "r"(sz));
}
__device__ __forceinline__ void cp8(void* dst, const void* src) {
    uint32_t d = (uint32_t)__cvta_generic_to_shared(dst);
    asm volatile("cp.async.ca.shared.global [%0], [%1], 8;" :: "r"(d), "l"(src));
}
#define CP_COMMIT() asm volatile("cp.async.commit_group;" ::: "memory")
#define CP_WAIT1()  asm volatile("cp.async.wait_group 1;" ::: "memory")
#define CP_WAIT0()  asm volatile("cp.async.wait_group 0;" ::: "memory")

// ---------------------------------------------------------------------------
// Fused: u transpose/split + inp passthrough (blocks < 1024), weight splits
// (blocks >= 1024).
__global__ void k_pre(const float* __restrict__ st, float* __restrict__ out_inp,
                      const float* __restrict__ w_in,
                      const float* __restrict__ w_out,
                      const float* __restrict__ to_w) {
    int bid = blockIdx.x;
    int tid = threadIdx.x;
    if (bid < 1024) {
        int row = bid;
        int b = row >> 6, g = row & 63;
        int h = tid >> 6, c = tid & 63;
        size_t si = (((size_t)(b*8 + h)*64) + g)*64 + c;
        float v = st[si];
        out_inp[si] = v;
        __nv_bfloat16 vh, vl;
        bsplit(v, vh, vl);
        S_uhi[row*DM512 + tid] = vh;
        S_ulo[row*DM512 + tid] = vl;
    } else {
        int i = (bid - 1024)*512 + tid;
        if (i < DINPROJ*DM512) {
            __nv_bfloat16 h, l;
            bsplit(w_in[i], h, l);
            S_W1hi[i] = h; S_W1lo[i] = l;
        }
        if (i < DM512*DM512) {
            __nv_bfloat16 h, l;
            bsplit(w_out[i], h, l);
            S_W2hi[i] = h; S_W2lo[i] = l;
            bsplit(to_w[i], h, l);
            S_Whi[i] = h; S_Wlo[i] = l;
        }
    }
}

// ---------------------------------------------------------------------------
// Presplit GEMM, BM=64, BN=128. mode 0: C[m,n] fp32. mode 1: split bf16 to
// S_outhi/S_outlo + permuted outp output (out-projection epilogue).
#define GS_SMEM 61440
__global__ __launch_bounds__(256) void k_gemm_sp64(
    const __nv_bfloat16* __restrict__ Ahi, const __nv_bfloat16* __restrict__ Alo,
    const __nv_bfloat16* __restrict__ Bhi, const __nv_bfloat16* __restrict__ Blo,
    float* __restrict__ C, int N, int mode, float* __restrict__ outp)
{
    extern __shared__ __nv_bfloat16 smG[];
    GDC_WAIT();
    int tid = threadIdx.x;
    int wid = tid >> 5, lane = tid & 31;
    int warp_m = wid & 1, warp_n = wid >> 1;
    int lr = lane >> 2;
    int lk = (lane & 3) * 2;
    size_t rbase = (size_t)blockIdx.x * 64;
    int n0 = blockIdx.y * 128;

    const int BUF = (2*64 + 2*128)*40;
    int m_st = tid >> 2;
    int kp_st = tid & 3;

    auto stage = [&](int kc, int buf) {
        __nv_bfloat16* Ah = smG + buf*BUF;
        __nv_bfloat16* Al = Ah + 64*40;
        __nv_bfloat16* Wh = Al + 64*40;
        __nv_bfloat16* Wl = Wh + 128*40;
        int kofs = kc*32 + kp_st*8;
        {
            size_t ga = (rbase + m_st)*512 + kofs;
            cp16(&Ah[m_st*40 + kp_st*8], &Ahi[ga]);
            cp16(&Al[m_st*40 + kp_st*8], &Alo[ga]);
        }
        #pragma unroll
        for (int p = 0; p < 2; ++p) {
            int m = m_st + p*64;
            size_t gw = (size_t)(n0 + m)*512 + kofs;
            cp16(&Wh[m*40 + kp_st*8], &Bhi[gw]);
            cp16(&Wl[m*40 + kp_st*8], &Blo[gw]);
        }
    };

    float acc[2][4][4];
    #pragma unroll
    for (int mt = 0; mt < 2; ++mt)
        #pragma unroll
        for (int nt = 0; nt < 4; ++nt)
            #pragma unroll
            for (int q = 0; q < 4; ++q) acc[mt][nt][q] = 0.f;

    stage(0, 0);
    CP_COMMIT();

    for (int kc = 0; kc < 16; ++kc) {
        int cur = kc & 1;
        if (kc < 15) { stage(kc + 1, cur ^ 1); CP_COMMIT(); CP_WAIT1(); }
        else         { CP_WAIT0(); }
        __syncthreads();

        __nv_bfloat16* Ah = smG + cur*BUF;
        __nv_bfloat16* Al = Ah + 64*40;
        __nv_bfloat16* Wh = Al + 64*40;
        __nv_bfloat16* Wl = Wh + 128*40;

        #pragma unroll
        for (int ks = 0; ks < 2; ++ks) {
            int k0 = ks*16;
            uint32_t ah[2][4], al[2][4], bh[4][2], bl[4][2];
            #pragma unroll
            for (int mt = 0; mt < 2; ++mt) {
                int rb = warp_m*32 + mt*16 + lr;
                const __nv_bfloat16* pa = &Ah[rb*40 + k0 + lk];
                ah[mt][0] = *(const uint32_t*)pa;
                ah[mt][1] = *(const uint32_t*)(pa + 8*40);
                ah[mt][2] = *(const uint32_t*)(pa + 8);
                ah[mt][3] = *(const uint32_t*)(pa + 8*40 + 8);
                const __nv_bfloat16* pl = &Al[rb*40 + k0 + lk];
                al[mt][0] = *(const uint32_t*)pl;
                al[mt][1] = *(const uint32_t*)(pl + 8*40);
                al[mt][2] = *(const uint32_t*)(pl + 8);
                al[mt][3] = *(const uint32_t*)(pl + 8*40 + 8);
            }
            #pragma unroll
            for (int nt = 0; nt < 4; ++nt) {
                int nb = warp_n*32 + nt*8 + lr;
                const __nv_bfloat16* pb = &Wh[nb*40 + k0 + lk];
                bh[nt][0] = *(const uint32_t*)pb;
                bh[nt][1] = *(const uint32_t*)(pb + 8);
                const __nv_bfloat16* pl = &Wl[nb*40 + k0 + lk];
                bl[nt][0] = *(const uint32_t*)pl;
                bl[nt][1] = *(const uint32_t*)(pl + 8);
            }
            #pragma unroll
            for (int mt = 0; mt < 2; ++mt)
                #pragma unroll
                for (int nt = 0; nt < 4; ++nt) {
                    mma16816(acc[mt][nt], ah[mt], bh[nt]);
                    mma16816(acc[mt][nt], ah[mt], bl[nt]);
                    mma16816(acc[mt][nt], al[mt], bh[nt]);
                }
        }
        __syncthreads();
    }

    #pragma unroll
    for (int mt = 0; mt < 2; ++mt) {
        int m = warp_m*32 + mt*16 + lr;
        #pragma unroll
        for (int nt = 0; nt < 4; ++nt) {
            int col = n0 + warp_n*32 + nt*8 + lk;
            if (col >= N) continue;
            size_t r0 = rbase + m;
            size_t r1 = r0 + 8;
            if (mode == 0) {
                float2 v0;
                v0.x = acc[mt][nt][0];
                v0.y = acc[mt][nt][1];
                *(float2*)&C[r0*N + col] = v0;
                float2 v1;
                v1.x = acc[mt][nt][2];
                v1.y = acc[mt][nt][3];
                *(float2*)&C[r1*N + col] = v1;
            } else {
                int h = col >> 6, c = col & 63;
                #pragma unroll
                for (int rr = 0; rr < 2; ++rr) {
                    size_t r = rr ? r1 : r0;
                    float v0 = acc[mt][nt][2*rr], v1 = acc[mt][nt][2*rr + 1];
                    __nv_bfloat16 h0, l0, h1, l1;
                    bsplit(v0, h0, l0);
                    bsplit(v1, h1, l1);
                    __nv_bfloat162 H; H.x = h0; H.y = h1;
                    __nv_bfloat162 L; L.x = l0; L.y = l1;
                    *(uint32_t*)&S_outhi[r*512 + col] = *(uint32_t*)&H;
                    *(uint32_t*)&S_outlo[r*512 + col] = *(uint32_t*)&L;
                    int b = (int)(r >> 6), g = (int)(r & 63);
                    float2 ov; ov.x = v0; ov.y = v1;
                    *(float2*)&outp[(((b*8 + h)*64 + g)*64) + c] = ov;
                }
            }
        }
    }
}

// ---------------------------------------------------------------------------
// Fused conv + scan v3, channel-split. Grid 128 = i*4 + q, 128 threads.
#define ZS2_LD 132
#define SC_SMEM (64*ZS2_LD*4 + 3*512*4 + 128*4)
__global__ __launch_bounds__(128) void k_scanc(
    const float* __restrict__ conv_w, const float* __restrict__ conv_b,
    const float* __restrict__ dt_bias, const float* __restrict__ A_log)
{
    extern __shared__ float smS[];
    GDC_WAIT();
    float* zs  = smS;
    float* dts = smS + 64*ZS2_LD;
    float* av  = dts + 512;
    float* dtv = av + 512;
    float* Bs  = dtv + 512;
    float* Cs  = Bs + 64;

    int cta = blockIdx.x;
    int i = cta >> 2;
    int q = cta & 3;
    int d = threadIdx.x;
    bool bw = (i >= 16);
    int b = bw ? i - 16 : i;
    int cbase = q*128;

    for (int p = 0; p < 33; ++p) {
        int idx = d + p*128;
        if (idx < 64*65) {
            int row = idx / 65, pr = idx - row*65;
            int gcol = (pr < 64) ? (512 + cbase + pr*2) : 1024;
            int scol = (pr < 64) ? (pr*2) : 128;
            cp8(&zs[row*ZS2_LD + scol],
                &S_zx[(size_t)(b*64 + row)*DINPROJ + gcol]);
        }
    }
    #pragma unroll
    for (int p = 0; p < 4; ++p) {
        int idx = d + p*128;
        int row = idx >> 3, hh = idx & 7;
        dts[idx] = S_zx[(b*64 + row)*DINPROJ + 1026 + (bw ? 8 : 0) + hh];
    }
    CP_COMMIT();
    CP_WAIT0();
    __syncthreads();

    if (d < 64) {
        int t = d;
        float acc = conv_b[512];
        #pragma unroll
        for (int k = 0; k < 3; ++k) {
            int tt = t + k - 2;
            if (tt >= 0) acc += conv_w[512*3 + k] * zs[tt*ZS2_LD + 128];
        }
        Bs[t] = acc / (1.f + expf(-acc));
    } else {
        int t = d - 64;
        float acc = conv_b[513];
        #pragma unroll
        for (int k = 0; k < 3; ++k) {
            int tt = t + k - 2;
            if (tt >= 0) acc += conv_w[513*3 + k] * zs[tt*ZS2_LD + 129];
        }
        Cs[t] = acc / (1.f + expf(-acc));
    }
    #pragma unroll
    for (int p = 0; p < 4; ++p) {
        int idx = d + p*128;
        int hh = idx & 7;
        float v = dts[idx] + dt_bias[hh];
        float dt = (v > 20.f) ? v : log1pf(expf(v));
        dtv[idx] = dt;
        av[idx]  = expf(dt * (-expf(A_log[hh])));
    }
    __syncthreads();

    int dch = cbase + d;
    int h = dch >> 6;
    float cb = conv_b[dch];
    float w0 = conv_w[dch*3], w1 = conv_w[dch*3 + 1], w2 = conv_w[dch*3 + 2];
    float hs = 0.f;
    S_ys[(size_t)(i*64)*512 + dch] = 0.f;

    if (!bw) {
        float zm2 = 0.f, zm1 = 0.f;
        #pragma unroll 4
        for (int t = 0; t < 64; ++t) {
            float z0 = zs[t*ZS2_LD + d];
            float cv = cb + w0*zm2 + w1*zm1 + w2*z0;
            float x  = cv / (1.f + expf(-cv));
            S_x[(size_t)(b*64 + t)*512 + dch] = x;
            hs = av[t*8 + h]*hs + dtv[t*8 + h]*Bs[t]*x;
            if (t < 63) S_ys[(size_t)(i*64 + t + 1)*512 + dch] = hs * Cs[t];
            zm2 = zm1; zm1 = z0;
        }
    } else {
        float z0  = zs[63*ZS2_LD + d];
        float zm1 = zs[62*ZS2_LD + d];
        float zm2 = zs[61*ZS2_LD + d];
        #pragma unroll 4
        for (int t = 0; t < 64; ++t) {
            int tt = 63 - t;
            float cv = cb + w0*zm2 + w1*zm1 + w2*z0;
            float x  = cv / (1.f + expf(-cv));
            hs = av[tt*8 + h]*hs + dtv[tt*8 + h]*Bs[tt]*x;
            if (t < 63) S_ys[(size_t)(i*64 + t + 1)*512 + dch] = hs * Cs[tt];
            z0 = zm1; zm1 = zm2;
            int nxt = tt - 3;
            zm2 = (nxt >= 0) ? zs[nxt*ZS2_LD + d] : 0.f;
        }
    }
}

// ---------------------------------------------------------------------------
// combine v2: warp-per-(head,half) dcoef reduction (5 SHFL/thread).
__global__ __launch_bounds__(512) void k_combine(
    const float* __restrict__ fc_D_w, const float* __restrict__ Dv,
    const float* __restrict__ norm_w)
{
    GDC_WAIT();
    int row = blockIdx.x;
    int b = row >> 6, t = row & 63;
    int d = threadIdx.x;
    int h = d >> 6;
    int lane = d & 31, wid = d >> 5;

    __shared__ float xs[512];
    __shared__ float wsum[16];
    __shared__ float dcf[8];
    __shared__ float rsum[16];
    __shared__ float rscale;

    float x  = S_x[row*512 + d];
    xs[d] = x;
    float z  = S_zx[row*DINPROJ + d];
    float yf = S_ys[row*512 + d];
    float yb = S_ys[((16 + b)*64 + (63 - t))*512 + d];
    __syncthreads();

    // dcoef[hw] partial: warp wid handles head hw = wid>>1, half = wid&1
    {
        int hw = wid >> 1, half = wid & 1;
        float s = 0.f;
        #pragma unroll
        for (int j = 0; j < 8; ++j) {
            int dd = half*256 + j*32 + lane;
            s += xs[dd] * fc_D_w[hw*512 + dd];
        }
        #pragma unroll
        for (int off = 16; off; off >>= 1) s += __shfl_xor_sync(0xffffffffu, s, off);
        if (lane == 0) wsum[wid] = s;
    }
    __syncthreads();
    if (d < 8) dcf[d] = wsum[2*d] + wsum[2*d + 1] + Dv[d];
    __syncthreads();

    float y = yf + yb + x * dcf[h];
    y *= z / (1.f + expf(-z));

    float sq = y*y;
    #pragma unroll
    for (int off = 16; off; off >>= 1) sq += __shfl_xor_sync(0xffffffffu, sq, off);
    if (lane == 0) rsum[wid] = sq;
    __syncthreads();
    if (d == 0) {
        float s = 0.f;
        #pragma unroll
        for (int w = 0; w < 16; ++w) s += rsum[w];
        rscale = rsqrtf(s / 512.f + 1e-5f);
    }
    __syncthreads();
    float yn = y * rscale * norm_w[d];
    __nv_bfloat16 vh, vl;
    bsplit(yn, vh, vl);
    S_ynhi[row*512 + d] = vh;
    S_ynlo[row*512 + d] = vl;
}

// ---------------------------------------------------------------------------
// prepP: Pt[b][d][h*64+g] = sum_c to_w[d, h*64+c] * out[(b*64+g)*512 + h*64+c]
#define PP_SMEM 55296
__global__ __launch_bounds__(256) void k_prepP() {
    extern __shared__ __nv_bfloat16 smP[];
    GDC_WAIT();
    __nv_bfloat16* Ahs = smP;
    __nv_bfloat16* Als = smP + 128*72;
    __nv_bfloat16* Bhs = smP + 2*128*72;
    __nv_bfloat16* Bls = Bhs + 64*72;

    int tid = threadIdx.x;
    int wid = tid >> 5, lane = tid & 31;
    int warp_m = wid & 1, warp_n = wid >> 1;
    int lr = lane >> 2;
    int lk = (lane & 3) * 2;
    int bh = blockIdx.x;
    int b = bh >> 3, h = bh & 7;
    int dbase = blockIdx.y * 128;

    {
        int r = tid >> 1, half = tid & 1;
        #pragma unroll
        for (int q0 = 0; q0 < 4; ++q0) {
            int q = half*4 + q0;
            size_t src = (size_t)(dbase + r)*512 + h*64 + q*8;
            cp16(&Ahs[r*72 + q*8], &S_Whi[src]);
            cp16(&Als[r*72 + q*8], &S_Wlo[src]);
        }
    }
    #pragma unroll
    for (int p = 0; p < 2; ++p) {
        int idx = tid + p*256;
        int g = idx >> 3, c8 = (idx & 7)*8;
        size_t src = (size_t)(b*64 + g)*512 + h*64 + c8;
        cp16(&Bhs[g*72 + c8], &S_outhi[src]);
        cp16(&Bls[g*72 + c8], &S_outlo[src]);
    }
    CP_COMMIT();
    CP_WAIT0();
    __syncthreads();

    float acc[4][2][4];
    #pragma unroll
    for (int mt = 0; mt < 4; ++mt)
        #pragma unroll
        for (int nt = 0; nt < 2; ++nt)
            #pragma unroll
            for (int q = 0; q < 4; ++q) acc[mt][nt][q] = 0.f;

    #pragma unroll
    for (int ks = 0; ks < 4; ++ks) {
        int k0 = ks*16;
        uint32_t ah[4][4], al[4][4], bhf[2][2], blf[2][2];
        #pragma unroll
        for (int mt = 0; mt < 4; ++mt) {
            int rb = warp_m*64 + mt*16 + lr;
            const __nv_bfloat16* pa = &Ahs[rb*72 + k0 + lk];
            ah[mt][0] = *(const uint32_t*)pa;
            ah[mt][1] = *(const uint32_t*)(pa + 8*72);
            ah[mt][2] = *(const uint32_t*)(pa + 8);
            ah[mt][3] = *(const uint32_t*)(pa + 8*72 + 8);
            const __nv_bfloat16* pl = &Als[rb*72 + k0 + lk];
            al[mt][0] = *(const uint32_t*)pl;
            al[mt][1] = *(const uint32_t*)(pl + 8*72);
            al[mt][2] = *(const uint32_t*)(pl + 8);
            al[mt][3] = *(const uint32_t*)(pl + 8*72 + 8);
        }
        #pragma unroll
        for (int nt = 0; nt < 2; ++nt) {
            int nb = warp_n*16 + nt*8 + lr;
            const __nv_bfloat16* pb = &Bhs[nb*72 + k0 + lk];
            bhf[nt][0] = *(const uint32_t*)pb;
            bhf[nt][1] = *(const uint32_t*)(pb + 8);
            const __nv_bfloat16* pl = &Bls[nb*72 + k0 + lk];
            blf[nt][0] = *(const uint32_t*)pl;
            blf[nt][1] = *(const uint32_t*)(pl + 8);
        }
        #pragma unroll
        for (int mt = 0; mt < 4; ++mt)
            #pragma unroll
            for (int nt = 0; nt < 2; ++nt) {
                mma16816(acc[mt][nt], ah[mt], bhf[nt]);
                mma16816(acc[mt][nt], ah[mt], blf[nt]);
                mma16816(acc[mt][nt], al[mt], bhf[nt]);
            }
    }

    #pragma unroll
    for (int mt = 0; mt < 4; ++mt) {
        int m = warp_m*64 + mt*16 + lr;
        #pragma unroll
        for (int nt = 0; nt < 2; ++nt) {
            int coln = warp_n*16 + nt*8 + lk;
            size_t base = ((size_t)b*512 + dbase + m)*512 + h*64 + coln;
            float2 v0;
            v0.x = to_tf32(acc[mt][nt][0]);
            v0.y = to_tf32(acc[mt][nt][1]);
            *(float2*)&S_Pt[base] = v0;
            float2 v1;
            v1.x = to_tf32(acc[mt][nt][2]);
            v1.y = to_tf32(acc[mt][nt][3]);
            *(float2*)&S_Pt[base + 8*512] = v1;
        }
    }
}

// ---------------------------------------------------------------------------
// Big GEMM v2 (tf32, M-tile 64, 3-stage all-cp.async, raw-bit A):
// out[b, n, dbase+col] = sum_hg sw[b,h,n,g]*Pt[b][d][hg] + bias
// Grid (196 = mtile*4+dchunk, 16 b), 256 threads (warp grid 2x4, 32x32 tiles).
// smem: 3 stages x (A[64][36] + B[128][36]) fp32 = 82944 B; 2 CTAs/SM.
#define BM_BUF  ((64 + 128)*36)
#define BM_SMEM (3*BM_BUF*4)
__global__ __launch_bounds__(256, 2) void k_bigmma(
    const float* __restrict__ sw, const float* __restrict__ bias,
    float* __restrict__ out)
{
    extern __shared__ float smB[];
    GDC_WAIT();
    int tid = threadIdx.x;
    int wid = tid >> 5, lane = tid & 31;
    int warp_m = wid & 1, warp_n = wid >> 1;
    int lr = lane >> 2;
    int lq = lane & 3;
    int dc = blockIdx.x & 3;
    int mt0 = blockIdx.x >> 2;
    int n0 = mt0 * 64;
    int b  = blockIdx.y;
    int dbase = dc * 128;

    int arow = tid >> 2;         // 0..63
    int aq = tid & 3;            // 8-float segment within 32-float chunk
    bool avalid = (n0 + arow) < NCTX;

    auto stageA = [&](int kc, int buf) {
        float* As = smB + buf*BM_BUF;
        int h = kc >> 1;
        int g0 = (kc & 1)*32 + aq*8;
        const float* src = sw + ((size_t)(b*8 + h)*NCTX + (avalid ? n0 + arow : 0))*64 + g0;
        float* dst = &As[arow*36 + aq*8];
        cp16p(dst,     src,     avalid);
        cp16p(dst + 4, src + 4, avalid);
    };
    auto stageB = [&](int kc, int buf) {
        float* Bs = smB + buf*BM_BUF + 64*36;
        #pragma unroll
        for (int p = 0; p < 4; ++p) {
            int idx = tid + p*256;
            int row = idx >> 3, q = idx & 7;
            size_t src = ((size_t)b*512 + dbase + row)*512 + kc*32 + q*4;
            cp16(&Bs[row*36 + q*4], &S_Pt[src]);
        }
    };

    float acc[2][4][4];
    #pragma unroll
    for (int mt = 0; mt < 2; ++mt)
        #pragma unroll
        for (int nt = 0; nt < 4; ++nt)
            #pragma unroll
            for (int q = 0; q < 4; ++q) acc[mt][nt][q] = 0.f;

    stageA(0, 0); stageB(0, 0); CP_COMMIT();
    stageA(1, 1); stageB(1, 1); CP_COMMIT();

    for (int kc = 0; kc < 16; ++kc) {
        if (kc < 15) { CP_WAIT1(); }
        else         { CP_WAIT0(); }
        __syncthreads();
        if (kc + 2 < 16) {
            int nb = (kc + 2) % 3;
            stageA(kc + 2, nb);
            stageB(kc + 2, nb);
            CP_COMMIT();
        }

        float* As = smB + (kc % 3)*BM_BUF;
        float* Bs = As + 64*36;

        #pragma unroll
        for (int ks = 0; ks < 4; ++ks) {
            int k0 = ks*8;
            uint32_t af[2][4], bf[4][2];
            #pragma unroll
            for (int mt = 0; mt < 2; ++mt) {
                int rb = warp_m*32 + mt*16 + lr;
                const float* pa = &As[rb*36 + k0 + lq];
                af[mt][0] = __float_as_uint(pa[0]);
                af[mt][1] = __float_as_uint(pa[8*36]);
                af[mt][2] = __float_as_uint(pa[4]);
                af[mt][3] = __float_as_uint(pa[8*36 + 4]);
            }
            #pragma unroll
            for (int nt = 0; nt < 4; ++nt) {
                int nb = warp_n*32 + nt*8 + lr;
                const float* pb = &Bs[nb*36 + k0 + lq];
                bf[nt][0] = __float_as_uint(pb[0]);
                bf[nt][1] = __float_as_uint(pb[4]);
            }
            #pragma unroll
            for (int mt = 0; mt < 2; ++mt)
                #pragma unroll
                for (int nt = 0; nt < 4; ++nt)
                    mma_tf32(acc[mt][nt], af[mt], bf[nt]);
        }
    }

    // epilogue
    #pragma unroll
    for (int mt = 0; mt < 2; ++mt) {
        int m = warp_m*32 + mt*16 + lr;
        #pragma unroll
        for (int nt = 0; nt < 4; ++nt) {
            int col = dbase + warp_n*32 + nt*8 + lq*2;
            float b0 = __ldg(&bias[col]);
            float b1 = __ldg(&bias[col + 1]);
            if (n0 + m < NCTX) {
                size_t r = (size_t)b*NCTX + n0 + m;
                float2 v;
                v.x = acc[mt][nt][0] + b0;
                v.y = acc[mt][nt][1] + b1;
                *(float2*)&out[r*512 + col] = v;
            }
            if (n0 + m + 8 < NCTX) {
                size_t r = (size_t)b*NCTX + n0 + m + 8;
                float2 v;
                v.x = acc[mt][nt][2] + b0;
                v.y = acc[mt][nt][3] + b1;
                *(float2*)&out[r*512 + col] = v;
            }
        }
    }
}

// ---------------------------------------------------------------------------
// Launch helper with PDL (programmatic stream serialization)
template <typename F, typename... Args>
static void launch_pdl(F fn, dim3 grid, dim3 block, size_t smem, Args... args) {
    cudaLaunchConfig_t cfg = {};
    cfg.gridDim = grid;
    cfg.blockDim = block;
    cfg.dynamicSmemBytes = smem;
    cfg.stream = 0;
    cudaLaunchAttribute attr[1];
    attr[0].id = cudaLaunchAttributeProgrammaticStreamSerialization;
    attr[0].val.programmaticStreamSerializationAllowed = 1;
    cfg.attrs = attr;
    cfg.numAttrs = 1;
    cudaLaunchKernelEx(&cfg, fn, args...);
}

extern "C" void kernel_launch(void* const* d_in, const int* in_sizes, int n_in,
                              void* d_out, int out_size) {
    const float* st     = (const float*)d_in[0];
    const float* sw     = (const float*)d_in[1];
    const float* w_in   = (const float*)d_in[2];
    const float* conv_w = (const float*)d_in[3];
    const float* conv_b = (const float*)d_in[4];
    const float* dt_bias= (const float*)d_in[5];
    const float* A_log  = (const float*)d_in[6];
    const float* Dv     = (const float*)d_in[7];
    const float* fc_D_w = (const float*)d_in[8];
    const float* norm_w = (const float*)d_in[9];
    const float* w_out  = (const float*)d_in[10];
    const float* to_w   = (const float*)d_in[11];
    const float* to_b   = (const float*)d_in[12];

    float* out       = (float*)d_out;
    float* out_final = out;
    float* out_inp   = out + (size_t)B16*NCTX*DM512;
    float* out_outp  = out_inp + (size_t)B16*8*64*64;

    float* pSzx;
    __nv_bfloat16 *pUh, *pUl, *pYh, *pYl, *pW1h, *pW1l, *pW2h, *pW2l;
    cudaGetSymbolAddress((void**)&pSzx, S_zx);
    cudaGetSymbolAddress((void**)&pUh, S_uhi);
    cudaGetSymbolAddress((void**)&pUl, S_ulo);
    cudaGetSymbolAddress((void**)&pYh, S_ynhi);
    cudaGetSymbolAddress((void**)&pYl, S_ynlo);
    cudaGetSymbolAddress((void**)&pW1h, S_W1hi);
    cudaGetSymbolAddress((void**)&pW1l, S_W1lo);
    cudaGetSymbolAddress((void**)&pW2h, S_W2hi);
    cudaGetSymbolAddress((void**)&pW2l, S_W2lo);

    k_pre<<<1024 + 1042, 512>>>(st, out_inp, w_in, w_out, to_w);

    cudaFuncSetAttribute(k_gemm_sp64, cudaFuncAttributeMaxDynamicSharedMemorySize, GS_SMEM);
    launch_pdl(k_gemm_sp64, dim3(16, 9), dim3(256), (size_t)GS_SMEM,
               (const __nv_bfloat16*)pUh, (const __nv_bfloat16*)pUl,
               (const __nv_bfloat16*)pW1h, (const __nv_bfloat16*)pW1l,
               pSzx, (int)DINPROJ, 0, (float*)nullptr);

    cudaFuncSetAttribute(k_scanc, cudaFuncAttributeMaxDynamicSharedMemorySize, SC_SMEM);
    launch_pdl(k_scanc, dim3(128), dim3(128), (size_t)SC_SMEM,
               conv_w, conv_b, dt_bias, A_log);

    launch_pdl(k_combine, dim3(B16*L64), dim3(512), (size_t)0, fc_D_w, Dv, norm_w);

    launch_pdl(k_gemm_sp64, dim3(16, 4), dim3(256), (size_t)GS_SMEM,
               (const __nv_bfloat16*)pYh, (const __nv_bfloat16*)pYl,
               (const __nv_bfloat16*)pW2h, (const __nv_bfloat16*)pW2l,
               (float*)nullptr, (int)DM512, 1, out_outp);

    cudaFuncSetAttribute(k_prepP, cudaFuncAttributeMaxDynamicSharedMemorySize, PP_SMEM);
    launch_pdl(k_prepP, dim3(128, 4), dim3(256), (size_t)PP_SMEM);

    cudaFuncSetAttribute(k_bigmma, cudaFuncAttributeMaxDynamicSharedMemorySize, BM_SMEM);
    launch_pdl(k_bigmma, dim3(4*((NCTX + 63)/64), B16), dim3(256), (size_t)BM_SMEM,
               sw, to_b, out_final);
}

// round 16
// speedup vs baseline: 1.0220x; 1.0220x over previous
#include <cuda_runtime.h>
#include <cuda_bf16.h>
#include <math.h>
#include <stdint.h>

// Problem constants
#define B16    16
#define L64    64
#define DM512  512
#define NCTX   3131
#define DINPROJ 1042
#define CONVDIM 514
#define MROWS  50096            // 16*3131

// Scratch (static device arrays; zero-initialized, allocation-free)
__device__ float S_zx [B16*L64*DINPROJ];
__device__ float S_x  [B16*L64*DM512];
__device__ float S_ys [2*B16*L64*DM512];
// split-bf16 operands (pre-pipeline)
__device__ __nv_bfloat16 S_uhi [B16*L64*DM512];
__device__ __nv_bfloat16 S_ulo [B16*L64*DM512];
__device__ __nv_bfloat16 S_ynhi[B16*L64*DM512];
__device__ __nv_bfloat16 S_ynlo[B16*L64*DM512];
__device__ __nv_bfloat16 S_outhi[B16*L64*DM512];
__device__ __nv_bfloat16 S_outlo[B16*L64*DM512];
__device__ __nv_bfloat16 S_W1hi[1152*DM512];
__device__ __nv_bfloat16 S_W1lo[1152*DM512];
__device__ __nv_bfloat16 S_W2hi[DM512*DM512];
__device__ __nv_bfloat16 S_W2lo[DM512*DM512];
__device__ __nv_bfloat16 S_Whi [DM512*DM512];
__device__ __nv_bfloat16 S_Wlo [DM512*DM512];
// Pt fp32 (tf32-pre-rounded): Pt[b][d][hg], natural layout
__device__ float S_Pt[(size_t)B16*DM512*DM512];

// ---- helpers ---------------------------------------------------------------
#define GDC_WAIT() asm volatile("griddepcontrol.wait;" ::: "memory")

__device__ __forceinline__ void mma16816(float* c, const uint32_t* a, const uint32_t* b) {
    asm volatile(
        "mma.sync.aligned.m16n8k16.row.col.f32.bf16.bf16.f32 "
        "{%0,%1,%2,%3}, {%4,%5,%6,%7}, {%8,%9}, {%0,%1,%2,%3};"
        : "+f"(c[0]), "+f"(c[1]), "+f"(c[2]), "+f"(c[3])
        : "r"(a[0]), "r"(a[1]), "r"(a[2]), "r"(a[3]), "r"(b[0]), "r"(b[1]));
}
__device__ __forceinline__ void mma_tf32(float* c, const uint32_t* a, const uint32_t* b) {
    asm volatile(
        "mma.sync.aligned.m16n8k8.row.col.f32.tf32.tf32.f32 "
        "{%0,%1,%2,%3}, {%4,%5,%6,%7}, {%8,%9}, {%0,%1,%2,%3};"
        : "+f"(c[0]), "+f"(c[1]), "+f"(c[2]), "+f"(c[3])
        : "r"(a[0]), "r"(a[1]), "r"(a[2]), "r"(a[3]), "r"(b[0]), "r"(b[1]));
}
__device__ __forceinline__ float to_tf32(float x) {
    uint32_t r;
    asm("cvt.rna.tf32.f32 %0, %1;" : "=r"(r) : "f"(x));
    return __uint_as_float(r);
}
__device__ __forceinline__ void bsplit(float v, __nv_bfloat16& h, __nv_bfloat16& l) {
    h = __float2bfloat16(v);
    l = __float2bfloat16(v - __bfloat162float(h));
}
__device__ __forceinline__ void cp16(void* dst, const void* src) {
    uint32_t d = (uint32_t)__cvta_generic_to_shared(dst);
    asm volatile("cp.async.cg.shared.global [%0], [%1], 16;" :: "r"(d), "l"(src));
}
// predicated 16B cp.async: src_size=0 zero-fills dst (OOB rows)
__device__ __forceinline__ void cp16p(void* dst, const void* src, bool pred) {
    uint32_t d = (uint32_t)__cvta_generic_to_shared(dst);
    int sz = pred ? 16 : 0;
    asm volatile("cp.async.cg.shared.global [%0], [%1], 16, %2;" :: "r"(d), "l"(src), "r"(sz));
}
__device__ __forceinline__ void cp8(void* dst, const void* src) {
    uint32_t d = (uint32_t)__cvta_generic_to_shared(dst);
    asm volatile("cp.async.ca.shared.global [%0], [%1], 8;" :: "r"(d), "l"(src));
}
#define CP_COMMIT() asm volatile("cp.async.commit_group;" ::: "memory")
#define CP_WAIT1()  asm volatile("cp.async.wait_group 1;" ::: "memory")
#define CP_WAIT0()  asm volatile("cp.async.wait_group 0;" ::: "memory")

// ---------------------------------------------------------------------------
// Fused: u transpose/split + inp passthrough (blocks < 1024), weight splits
// (blocks >= 1024).
__global__ void k_pre(const float* __restrict__ st, float* __restrict__ out_inp,
                      const float* __restrict__ w_in,
                      const float* __restrict__ w_out,
                      const float* __restrict__ to_w) {
    int bid = blockIdx.x;
    int tid = threadIdx.x;
    if (bid < 1024) {
        int row = bid;
        int b = row >> 6, g = row & 63;
        int h = tid >> 6, c = tid & 63;
        size_t si = (((size_t)(b*8 + h)*64) + g)*64 + c;
        float v = st[si];
        out_inp[si] = v;
        __nv_bfloat16 vh, vl;
        bsplit(v, vh, vl);
        S_uhi[row*DM512 + tid] = vh;
        S_ulo[row*DM512 + tid] = vl;
    } else {
        int i = (bid - 1024)*512 + tid;
        if (i < DINPROJ*DM512) {
            __nv_bfloat16 h, l;
            bsplit(w_in[i], h, l);
            S_W1hi[i] = h; S_W1lo[i] = l;
        }
        if (i < DM512*DM512) {
            __nv_bfloat16 h, l;
            bsplit(w_out[i], h, l);
            S_W2hi[i] = h; S_W2lo[i] = l;
            bsplit(to_w[i], h, l);
            S_Whi[i] = h; S_Wlo[i] = l;
        }
    }
}

// ---------------------------------------------------------------------------
// Presplit GEMM, BM=64, BN=128. mode 0: C[m,n] fp32. mode 1: split bf16 to
// S_outhi/S_outlo + permuted outp output (out-projection epilogue).
#define GS_SMEM 61440
__global__ __launch_bounds__(256) void k_gemm_sp64(
    const __nv_bfloat16* __restrict__ Ahi, const __nv_bfloat16* __restrict__ Alo,
    const __nv_bfloat16* __restrict__ Bhi, const __nv_bfloat16* __restrict__ Blo,
    float* __restrict__ C, int N, int mode, float* __restrict__ outp)
{
    extern __shared__ __nv_bfloat16 smG[];
    GDC_WAIT();
    int tid = threadIdx.x;
    int wid = tid >> 5, lane = tid & 31;
    int warp_m = wid & 1, warp_n = wid >> 1;
    int lr = lane >> 2;
    int lk = (lane & 3) * 2;
    size_t rbase = (size_t)blockIdx.x * 64;
    int n0 = blockIdx.y * 128;

    const int BUF = (2*64 + 2*128)*40;
    int m_st = tid >> 2;
    int kp_st = tid & 3;

    auto stage = [&](int kc, int buf) {
        __nv_bfloat16* Ah = smG + buf*BUF;
        __nv_bfloat16* Al = Ah + 64*40;
        __nv_bfloat16* Wh = Al + 64*40;
        __nv_bfloat16* Wl = Wh + 128*40;
        int kofs = kc*32 + kp_st*8;
        {
            size_t ga = (rbase + m_st)*512 + kofs;
            cp16(&Ah[m_st*40 + kp_st*8], &Ahi[ga]);
            cp16(&Al[m_st*40 + kp_st*8], &Alo[ga]);
        }
        #pragma unroll
        for (int p = 0; p < 2; ++p) {
            int m = m_st + p*64;
            size_t gw = (size_t)(n0 + m)*512 + kofs;
            cp16(&Wh[m*40 + kp_st*8], &Bhi[gw]);
            cp16(&Wl[m*40 + kp_st*8], &Blo[gw]);
        }
    };

    float acc[2][4][4];
    #pragma unroll
    for (int mt = 0; mt < 2; ++mt)
        #pragma unroll
        for (int nt = 0; nt < 4; ++nt)
            #pragma unroll
            for (int q = 0; q < 4; ++q) acc[mt][nt][q] = 0.f;

    stage(0, 0);
    CP_COMMIT();

    for (int kc = 0; kc < 16; ++kc) {
        int cur = kc & 1;
        if (kc < 15) { stage(kc + 1, cur ^ 1); CP_COMMIT(); CP_WAIT1(); }
        else         { CP_WAIT0(); }
        __syncthreads();

        __nv_bfloat16* Ah = smG + cur*BUF;
        __nv_bfloat16* Al = Ah + 64*40;
        __nv_bfloat16* Wh = Al + 64*40;
        __nv_bfloat16* Wl = Wh + 128*40;

        #pragma unroll
        for (int ks = 0; ks < 2; ++ks) {
            int k0 = ks*16;
            uint32_t ah[2][4], al[2][4], bh[4][2], bl[4][2];
            #pragma unroll
            for (int mt = 0; mt < 2; ++mt) {
                int rb = warp_m*32 + mt*16 + lr;
                const __nv_bfloat16* pa = &Ah[rb*40 + k0 + lk];
                ah[mt][0] = *(const uint32_t*)pa;
                ah[mt][1] = *(const uint32_t*)(pa + 8*40);
                ah[mt][2] = *(const uint32_t*)(pa + 8);
                ah[mt][3] = *(const uint32_t*)(pa + 8*40 + 8);
                const __nv_bfloat16* pl = &Al[rb*40 + k0 + lk];
                al[mt][0] = *(const uint32_t*)pl;
                al[mt][1] = *(const uint32_t*)(pl + 8*40);
                al[mt][2] = *(const uint32_t*)(pl + 8);
                al[mt][3] = *(const uint32_t*)(pl + 8*40 + 8);
            }
            #pragma unroll
            for (int nt = 0; nt < 4; ++nt) {
                int nb = warp_n*32 + nt*8 + lr;
                const __nv_bfloat16* pb = &Wh[nb*40 + k0 + lk];
                bh[nt][0] = *(const uint32_t*)pb;
                bh[nt][1] = *(const uint32_t*)(pb + 8);
                const __nv_bfloat16* pl = &Wl[nb*40 + k0 + lk];
                bl[nt][0] = *(const uint32_t*)pl;
                bl[nt][1] = *(const uint32_t*)(pl + 8);
            }
            #pragma unroll
            for (int mt = 0; mt < 2; ++mt)
                #pragma unroll
                for (int nt = 0; nt < 4; ++nt) {
                    mma16816(acc[mt][nt], ah[mt], bh[nt]);
                    mma16816(acc[mt][nt], ah[mt], bl[nt]);
                    mma16816(acc[mt][nt], al[mt], bh[nt]);
                }
        }
        __syncthreads();
    }

    #pragma unroll
    for (int mt = 0; mt < 2; ++mt) {
        int m = warp_m*32 + mt*16 + lr;
        #pragma unroll
        for (int nt = 0; nt < 4; ++nt) {
            int col = n0 + warp_n*32 + nt*8 + lk;
            if (col >= N) continue;
            size_t r0 = rbase + m;
            size_t r1 = r0 + 8;
            if (mode == 0) {
                float2 v0;
                v0.x = acc[mt][nt][0];
                v0.y = acc[mt][nt][1];
                *(float2*)&C[r0*N + col] = v0;
                float2 v1;
                v1.x = acc[mt][nt][2];
                v1.y = acc[mt][nt][3];
                *(float2*)&C[r1*N + col] = v1;
            } else {
                int h = col >> 6, c = col & 63;
                #pragma unroll
                for (int rr = 0; rr < 2; ++rr) {
                    size_t r = rr ? r1 : r0;
                    float v0 = acc[mt][nt][2*rr], v1 = acc[mt][nt][2*rr + 1];
                    __nv_bfloat16 h0, l0, h1, l1;
                    bsplit(v0, h0, l0);
                    bsplit(v1, h1, l1);
                    __nv_bfloat162 H; H.x = h0; H.y = h1;
                    __nv_bfloat162 L; L.x = l0; L.y = l1;
                    *(uint32_t*)&S_outhi[r*512 + col] = *(uint32_t*)&H;
                    *(uint32_t*)&S_outlo[r*512 + col] = *(uint32_t*)&L;
                    int b = (int)(r >> 6), g = (int)(r & 63);
                    float2 ov; ov.x = v0; ov.y = v1;
                    *(float2*)&outp[(((b*8 + h)*64 + g)*64) + c] = ov;
                }
            }
        }
    }
}

// ---------------------------------------------------------------------------
// Fused conv + scan v3, channel-split. Grid 128 = i*4 + q, 128 threads.
#define ZS2_LD 132
#define SC_SMEM (64*ZS2_LD*4 + 3*512*4 + 128*4)
__global__ __launch_bounds__(128) void k_scanc(
    const float* __restrict__ conv_w, const float* __restrict__ conv_b,
    const float* __restrict__ dt_bias, const float* __restrict__ A_log)
{
    extern __shared__ float smS[];
    GDC_WAIT();
    float* zs  = smS;
    float* dts = smS + 64*ZS2_LD;
    float* av  = dts + 512;
    float* dtv = av + 512;
    float* Bs  = dtv + 512;
    float* Cs  = Bs + 64;

    int cta = blockIdx.x;
    int i = cta >> 2;
    int q = cta & 3;
    int d = threadIdx.x;
    bool bw = (i >= 16);
    int b = bw ? i - 16 : i;
    int cbase = q*128;

    for (int p = 0; p < 33; ++p) {
        int idx = d + p*128;
        if (idx < 64*65) {
            int row = idx / 65, pr = idx - row*65;
            int gcol = (pr < 64) ? (512 + cbase + pr*2) : 1024;
            int scol = (pr < 64) ? (pr*2) : 128;
            cp8(&zs[row*ZS2_LD + scol],
                &S_zx[(size_t)(b*64 + row)*DINPROJ + gcol]);
        }
    }
    #pragma unroll
    for (int p = 0; p < 4; ++p) {
        int idx = d + p*128;
        int row = idx >> 3, hh = idx & 7;
        dts[idx] = S_zx[(b*64 + row)*DINPROJ + 1026 + (bw ? 8 : 0) + hh];
    }
    CP_COMMIT();
    CP_WAIT0();
    __syncthreads();

    if (d < 64) {
        int t = d;
        float acc = conv_b[512];
        #pragma unroll
        for (int k = 0; k < 3; ++k) {
            int tt = t + k - 2;
            if (tt >= 0) acc += conv_w[512*3 + k] * zs[tt*ZS2_LD + 128];
        }
        Bs[t] = acc / (1.f + expf(-acc));
    } else {
        int t = d - 64;
        float acc = conv_b[513];
        #pragma unroll
        for (int k = 0; k < 3; ++k) {
            int tt = t + k - 2;
            if (tt >= 0) acc += conv_w[513*3 + k] * zs[tt*ZS2_LD + 129];
        }
        Cs[t] = acc / (1.f + expf(-acc));
    }
    #pragma unroll
    for (int p = 0; p < 4; ++p) {
        int idx = d + p*128;
        int hh = idx & 7;
        float v = dts[idx] + dt_bias[hh];
        float dt = (v > 20.f) ? v : log1pf(expf(v));
        dtv[idx] = dt;
        av[idx]  = expf(dt * (-expf(A_log[hh])));
    }
    __syncthreads();

    int dch = cbase + d;
    int h = dch >> 6;
    float cb = conv_b[dch];
    float w0 = conv_w[dch*3], w1 = conv_w[dch*3 + 1], w2 = conv_w[dch*3 + 2];
    float hs = 0.f;
    S_ys[(size_t)(i*64)*512 + dch] = 0.f;

    if (!bw) {
        float zm2 = 0.f, zm1 = 0.f;
        #pragma unroll 4
        for (int t = 0; t < 64; ++t) {
            float z0 = zs[t*ZS2_LD + d];
            float cv = cb + w0*zm2 + w1*zm1 + w2*z0;
            float x  = cv / (1.f + expf(-cv));
            S_x[(size_t)(b*64 + t)*512 + dch] = x;
            hs = av[t*8 + h]*hs + dtv[t*8 + h]*Bs[t]*x;
            if (t < 63) S_ys[(size_t)(i*64 + t + 1)*512 + dch] = hs * Cs[t];
            zm2 = zm1; zm1 = z0;
        }
    } else {
        float z0  = zs[63*ZS2_LD + d];
        float zm1 = zs[62*ZS2_LD + d];
        float zm2 = zs[61*ZS2_LD + d];
        #pragma unroll 4
        for (int t = 0; t < 64; ++t) {
            int tt = 63 - t;
            float cv = cb + w0*zm2 + w1*zm1 + w2*z0;
            float x  = cv / (1.f + expf(-cv));
            hs = av[tt*8 + h]*hs + dtv[tt*8 + h]*Bs[tt]*x;
            if (t < 63) S_ys[(size_t)(i*64 + t + 1)*512 + dch] = hs * Cs[tt];
            z0 = zm1; zm1 = zm2;
            int nxt = tt - 3;
            zm2 = (nxt >= 0) ? zs[nxt*ZS2_LD + d] : 0.f;
        }
    }
}

// ---------------------------------------------------------------------------
// combine v2: warp-per-(head,half) dcoef reduction (5 SHFL/thread).
__global__ __launch_bounds__(512) void k_combine(
    const float* __restrict__ fc_D_w, const float* __restrict__ Dv,
    const float* __restrict__ norm_w)
{
    GDC_WAIT();
    int row = blockIdx.x;
    int b = row >> 6, t = row & 63;
    int d = threadIdx.x;
    int h = d >> 6;
    int lane = d & 31, wid = d >> 5;

    __shared__ float xs[512];
    __shared__ float wsum[16];
    __shared__ float dcf[8];
    __shared__ float rsum[16];
    __shared__ float rscale;

    float x  = S_x[row*512 + d];
    xs[d] = x;
    float z  = S_zx[row*DINPROJ + d];
    float yf = S_ys[row*512 + d];
    float yb = S_ys[((16 + b)*64 + (63 - t))*512 + d];
    __syncthreads();

    {
        int hw = wid >> 1, half = wid & 1;
        float s = 0.f;
        #pragma unroll
        for (int j = 0; j < 8; ++j) {
            int dd = half*256 + j*32 + lane;
            s += xs[dd] * fc_D_w[hw*512 + dd];
        }
        #pragma unroll
        for (int off = 16; off; off >>= 1) s += __shfl_xor_sync(0xffffffffu, s, off);
        if (lane == 0) wsum[wid] = s;
    }
    __syncthreads();
    if (d < 8) dcf[d] = wsum[2*d] + wsum[2*d + 1] + Dv[d];
    __syncthreads();

    float y = yf + yb + x * dcf[h];
    y *= z / (1.f + expf(-z));

    float sq = y*y;
    #pragma unroll
    for (int off = 16; off; off >>= 1) sq += __shfl_xor_sync(0xffffffffu, sq, off);
    if (lane == 0) rsum[wid] = sq;
    __syncthreads();
    if (d == 0) {
        float s = 0.f;
        #pragma unroll
        for (int w = 0; w < 16; ++w) s += rsum[w];
        rscale = rsqrtf(s / 512.f + 1e-5f);
    }
    __syncthreads();
    float yn = y * rscale * norm_w[d];
    __nv_bfloat16 vh, vl;
    bsplit(yn, vh, vl);
    S_ynhi[row*512 + d] = vh;
    S_ynlo[row*512 + d] = vl;
}

// ---------------------------------------------------------------------------
// prepP: Pt[b][d][h*64+g] = sum_c to_w[d, h*64+c] * out[(b*64+g)*512 + h*64+c]
#define PP_SMEM 55296
__global__ __launch_bounds__(256) void k_prepP() {
    extern __shared__ __nv_bfloat16 smP[];
    GDC_WAIT();
    __nv_bfloat16* Ahs = smP;
    __nv_bfloat16* Als = smP + 128*72;
    __nv_bfloat16* Bhs = smP + 2*128*72;
    __nv_bfloat16* Bls = Bhs + 64*72;

    int tid = threadIdx.x;
    int wid = tid >> 5, lane = tid & 31;
    int warp_m = wid & 1, warp_n = wid >> 1;
    int lr = lane >> 2;
    int lk = (lane & 3) * 2;
    int bh = blockIdx.x;
    int b = bh >> 3, h = bh & 7;
    int dbase = blockIdx.y * 128;

    {
        int r = tid >> 1, half = tid & 1;
        #pragma unroll
        for (int q0 = 0; q0 < 4; ++q0) {
            int q = half*4 + q0;
            size_t src = (size_t)(dbase + r)*512 + h*64 + q*8;
            cp16(&Ahs[r*72 + q*8], &S_Whi[src]);
            cp16(&Als[r*72 + q*8], &S_Wlo[src]);
        }
    }
    #pragma unroll
    for (int p = 0; p < 2; ++p) {
        int idx = tid + p*256;
        int g = idx >> 3, c8 = (idx & 7)*8;
        size_t src = (size_t)(b*64 + g)*512 + h*64 + c8;
        cp16(&Bhs[g*72 + c8], &S_outhi[src]);
        cp16(&Bls[g*72 + c8], &S_outlo[src]);
    }
    CP_COMMIT();
    CP_WAIT0();
    __syncthreads();

    float acc[4][2][4];
    #pragma unroll
    for (int mt = 0; mt < 4; ++mt)
        #pragma unroll
        for (int nt = 0; nt < 2; ++nt)
            #pragma unroll
            for (int q = 0; q < 4; ++q) acc[mt][nt][q] = 0.f;

    #pragma unroll
    for (int ks = 0; ks < 4; ++ks) {
        int k0 = ks*16;
        uint32_t ah[4][4], al[4][4], bhf[2][2], blf[2][2];
        #pragma unroll
        for (int mt = 0; mt < 4; ++mt) {
            int rb = warp_m*64 + mt*16 + lr;
            const __nv_bfloat16* pa = &Ahs[rb*72 + k0 + lk];
            ah[mt][0] = *(const uint32_t*)pa;
            ah[mt][1] = *(const uint32_t*)(pa + 8*72);
            ah[mt][2] = *(const uint32_t*)(pa + 8);
            ah[mt][3] = *(const uint32_t*)(pa + 8*72 + 8);
            const __nv_bfloat16* pl = &Als[rb*72 + k0 + lk];
            al[mt][0] = *(const uint32_t*)pl;
            al[mt][1] = *(const uint32_t*)(pl + 8*72);
            al[mt][2] = *(const uint32_t*)(pl + 8);
            al[mt][3] = *(const uint32_t*)(pl + 8*72 + 8);
        }
        #pragma unroll
        for (int nt = 0; nt < 2; ++nt) {
            int nb = warp_n*16 + nt*8 + lr;
            const __nv_bfloat16* pb = &Bhs[nb*72 + k0 + lk];
            bhf[nt][0] = *(const uint32_t*)pb;
            bhf[nt][1] = *(const uint32_t*)(pb + 8);
            const __nv_bfloat16* pl = &Bls[nb*72 + k0 + lk];
            blf[nt][0] = *(const uint32_t*)pl;
            blf[nt][1] = *(const uint32_t*)(pl + 8);
        }
        #pragma unroll
        for (int mt = 0; mt < 4; ++mt)
            #pragma unroll
            for (int nt = 0; nt < 2; ++nt) {
                mma16816(acc[mt][nt], ah[mt], bhf[nt]);
                mma16816(acc[mt][nt], ah[mt], blf[nt]);
                mma16816(acc[mt][nt], al[mt], bhf[nt]);
            }
    }

    #pragma unroll
    for (int mt = 0; mt < 4; ++mt) {
        int m = warp_m*64 + mt*16 + lr;
        #pragma unroll
        for (int nt = 0; nt < 2; ++nt) {
            int coln = warp_n*16 + nt*8 + lk;
            size_t base = ((size_t)b*512 + dbase + m)*512 + h*64 + coln;
            float2 v0;
            v0.x = to_tf32(acc[mt][nt][0]);
            v0.y = to_tf32(acc[mt][nt][1]);
            *(float2*)&S_Pt[base] = v0;
            float2 v1;
            v1.x = to_tf32(acc[mt][nt][2]);
            v1.y = to_tf32(acc[mt][nt][3]);
            *(float2*)&S_Pt[base + 8*512] = v1;
        }
    }
}

// ---------------------------------------------------------------------------
// Big GEMM (tf32, M-tile 128, 3-stage all-cp.async pipeline, raw-bit A):
// out[b, n, dbase+col] = sum_hg sw[b,h,n,g]*Pt[b][d][hg] + bias
// Grid (100 = mtile*4+dchunk, 16 b), 256 threads. BK=32, prefetch distance 2.
#define BM_BUF  (2*128*36)
#define BM_SMEM (3*BM_BUF*4)
__global__ __launch_bounds__(256, 2) void k_bigmma(
    const float* __restrict__ sw, const float* __restrict__ bias,
    float* __restrict__ out)
{
    extern __shared__ float smB[];
    GDC_WAIT();
    int tid = threadIdx.x;
    int wid = tid >> 5, lane = tid & 31;
    int warp_m = wid & 1, warp_n = wid >> 1;
    int lr = lane >> 2;
    int lq = lane & 3;
    int dc = blockIdx.x & 3;
    int mt0 = blockIdx.x >> 2;
    int n0 = mt0 * 128;
    int b  = blockIdx.y;
    int dbase = dc * 128;

    int arow = tid >> 1;
    int ahalf = tid & 1;
    bool avalid = (n0 + arow) < NCTX;

    auto stageA = [&](int kc, int buf) {
        float* As = smB + buf*BM_BUF;
        int h = kc >> 1;
        int g0 = (kc & 1)*32 + ahalf*16;
        const float* src = sw + ((size_t)(b*8 + h)*NCTX + (avalid ? n0 + arow : 0))*64 + g0;
        float* dst = &As[arow*36 + ahalf*16];
        cp16p(dst,      src,      avalid);
        cp16p(dst + 4,  src + 4,  avalid);
        cp16p(dst + 8,  src + 8,  avalid);
        cp16p(dst + 12, src + 12, avalid);
    };
    auto stageB = [&](int kc, int buf) {
        float* Bs = smB + buf*BM_BUF + 128*36;
        #pragma unroll
        for (int p = 0; p < 4; ++p) {
            int idx = tid + p*256;
            int row = idx >> 3, q = idx & 7;
            size_t src = ((size_t)b*512 + dbase + row)*512 + kc*32 + q*4;
            cp16(&Bs[row*36 + q*4], &S_Pt[src]);
        }
    };

    float acc[4][4][4];
    #pragma unroll
    for (int mt = 0; mt < 4; ++mt)
        #pragma unroll
        for (int nt = 0; nt < 4; ++nt)
            #pragma unroll
            for (int q = 0; q < 4; ++q) acc[mt][nt][q] = 0.f;

    stageA(0, 0); stageB(0, 0); CP_COMMIT();
    stageA(1, 1); stageB(1, 1); CP_COMMIT();

    for (int kc = 0; kc < 16; ++kc) {
        if (kc < 15) { CP_WAIT1(); }
        else         { CP_WAIT0(); }
        __syncthreads();
        if (kc + 2 < 16) {
            int nb = (kc + 2) % 3;
            stageA(kc + 2, nb);
            stageB(kc + 2, nb);
            CP_COMMIT();
        }

        float* As = smB + (kc % 3)*BM_BUF;
        float* Bs = As + 128*36;

        #pragma unroll
        for (int ks = 0; ks < 4; ++ks) {
            int k0 = ks*8;
            uint32_t af[4][4], bf[4][2];
            #pragma unroll
            for (int mt = 0; mt < 4; ++mt) {
                int rb = warp_m*64 + mt*16 + lr;
                const float* pa = &As[rb*36 + k0 + lq];
                af[mt][0] = __float_as_uint(pa[0]);
                af[mt][1] = __float_as_uint(pa[8*36]);
                af[mt][2] = __float_as_uint(pa[4]);
                af[mt][3] = __float_as_uint(pa[8*36 + 4]);
            }
            #pragma unroll
            for (int nt = 0; nt < 4; ++nt) {
                int nb = warp_n*32 + nt*8 + lr;
                const float* pb = &Bs[nb*36 + k0 + lq];
                bf[nt][0] = __float_as_uint(pb[0]);
                bf[nt][1] = __float_as_uint(pb[4]);
            }
            #pragma unroll
            for (int mt = 0; mt < 4; ++mt)
                #pragma unroll
                for (int nt = 0; nt < 4; ++nt)
                    mma_tf32(acc[mt][nt], af[mt], bf[nt]);
        }
    }

    // epilogue
    #pragma unroll
    for (int mt = 0; mt < 4; ++mt) {
        int m = warp_m*64 + mt*16 + lr;
        #pragma unroll
        for (int nt = 0; nt < 4; ++nt) {
            int col = dbase + warp_n*32 + nt*8 + lq*2;
            float b0 = __ldg(&bias[col]);
            float b1 = __ldg(&bias[col + 1]);
            if (n0 + m < NCTX) {
                size_t r = (size_t)b*NCTX + n0 + m;
                float2 v;
                v.x = acc[mt][nt][0] + b0;
                v.y = acc[mt][nt][1] + b1;
                *(float2*)&out[r*512 + col] = v;
            }
            if (n0 + m + 8 < NCTX) {
                size_t r = (size_t)b*NCTX + n0 + m + 8;
                float2 v;
                v.x = acc[mt][nt][2] + b0;
                v.y = acc[mt][nt][3] + b1;
                *(float2*)&out[r*512 + col] = v;
            }
        }
    }
}

// ---------------------------------------------------------------------------
// Launch helper with PDL (programmatic stream serialization)
template <typename F, typename... Args>
static void launch_pdl(F fn, dim3 grid, dim3 block, size_t smem, Args... args) {
    cudaLaunchConfig_t cfg = {};
    cfg.gridDim = grid;
    cfg.blockDim = block;
    cfg.dynamicSmemBytes = smem;
    cfg.stream = 0;
    cudaLaunchAttribute attr[1];
    attr[0].id = cudaLaunchAttributeProgrammaticStreamSerialization;
    attr[0].val.programmaticStreamSerializationAllowed = 1;
    cfg.attrs = attr;
    cfg.numAttrs = 1;
    cudaLaunchKernelEx(&cfg, fn, args...);
}

extern "C" void kernel_launch(void* const* d_in, const int* in_sizes, int n_in,
                              void* d_out, int out_size) {
    const float* st     = (const float*)d_in[0];
    const float* sw     = (const float*)d_in[1];
    const float* w_in   = (const float*)d_in[2];
    const float* conv_w = (const float*)d_in[3];
    const float* conv_b = (const float*)d_in[4];
    const float* dt_bias= (const float*)d_in[5];
    const float* A_log  = (const float*)d_in[6];
    const float* Dv     = (const float*)d_in[7];
    const float* fc_D_w = (const float*)d_in[8];
    const float* norm_w = (const float*)d_in[9];
    const float* w_out  = (const float*)d_in[10];
    const float* to_w   = (const float*)d_in[11];
    const float* to_b   = (const float*)d_in[12];

    float* out       = (float*)d_out;
    float* out_final = out;
    float* out_inp   = out + (size_t)B16*NCTX*DM512;
    float* out_outp  = out_inp + (size_t)B16*8*64*64;

    float* pSzx;
    __nv_bfloat16 *pUh, *pUl, *pYh, *pYl, *pW1h, *pW1l, *pW2h, *pW2l;
    cudaGetSymbolAddress((void**)&pSzx, S_zx);
    cudaGetSymbolAddress((void**)&pUh, S_uhi);
    cudaGetSymbolAddress((void**)&pUl, S_ulo);
    cudaGetSymbolAddress((void**)&pYh, S_ynhi);
    cudaGetSymbolAddress((void**)&pYl, S_ynlo);
    cudaGetSymbolAddress((void**)&pW1h, S_W1hi);
    cudaGetSymbolAddress((void**)&pW1l, S_W1lo);
    cudaGetSymbolAddress((void**)&pW2h, S_W2hi);
    cudaGetSymbolAddress((void**)&pW2l, S_W2lo);

    k_pre<<<1024 + 1042, 512>>>(st, out_inp, w_in, w_out, to_w);

    cudaFuncSetAttribute(k_gemm_sp64, cudaFuncAttributeMaxDynamicSharedMemorySize, GS_SMEM);
    launch_pdl(k_gemm_sp64, dim3(16, 9), dim3(256), (size_t)GS_SMEM,
               (const __nv_bfloat16*)pUh, (const __nv_bfloat16*)pUl,
               (const __nv_bfloat16*)pW1h, (const __nv_bfloat16*)pW1l,
               pSzx, (int)DINPROJ, 0, (float*)nullptr);

    cudaFuncSetAttribute(k_scanc, cudaFuncAttributeMaxDynamicSharedMemorySize, SC_SMEM);
    launch_pdl(k_scanc, dim3(128), dim3(128), (size_t)SC_SMEM,
               conv_w, conv_b, dt_bias, A_log);

    launch_pdl(k_combine, dim3(B16*L64), dim3(512), (size_t)0, fc_D_w, Dv, norm_w);

    launch_pdl(k_gemm_sp64, dim3(16, 4), dim3(256), (size_t)GS_SMEM,
               (const __nv_bfloat16*)pYh, (const __nv_bfloat16*)pYl,
               (const __nv_bfloat16*)pW2h, (const __nv_bfloat16*)pW2l,
               (float*)nullptr, (int)DM512, 1, out_outp);

    cudaFuncSetAttribute(k_prepP, cudaFuncAttributeMaxDynamicSharedMemorySize, PP_SMEM);
    launch_pdl(k_prepP, dim3(128, 4), dim3(256), (size_t)PP_SMEM);

    cudaFuncSetAttribute(k_bigmma, cudaFuncAttributeMaxDynamicSharedMemorySize, BM_SMEM);
    launch_pdl(k_bigmma, dim3(4*((NCTX + 127)/128), B16), dim3(256), (size_t)BM_SMEM,
               sw, to_b, out_final);
}